// round 8
// baseline (speedup 1.0000x reference)
#include <cuda_runtime.h>
#include <cstdint>

#define B_ 32
#define T_ 1024
#define V_ 1000
#define L_ 128
#define NG_ 256           // time groups of 4 steps
#define SLOTS_ 129        // emission slots, 128 = blank
#define NEGF (-1e30f)
#define L2E_ 1.4426950408889634f
#define LN2_ 0.6931471805599453f

// scratch (allocation-free rule: __device__ globals)
// emissions, DP-native layout: [b][g][slot][4 timesteps], log2 domain
__device__ float g_E2[(size_t)B_ * NG_ * SLOTS_ * 4];
__device__ float g_partial[B_];

__device__ __forceinline__ float ex2f_(float x){ float y; asm("ex2.approx.f32 %0,%1;":"=f"(y):"f"(x)); return y; }
__device__ __forceinline__ float lg2f_(float x){ float y; asm("lg2.approx.f32 %0,%1;":"=f"(y):"f"(x)); return y; }
__device__ __forceinline__ float lse2_(float x, float y){
    float m = fmaxf(x, y);
    float d = fminf(x, y) - m;
    return m + lg2f_(1.0f + ex2f_(d));
}
__device__ __forceinline__ int ld_acq_(const int* p){
    int v; asm volatile("ld.acquire.cta.b32 %0, [%1];" : "=r"(v) : "l"(p) : "memory"); return v;
}
__device__ __forceinline__ void st_rel_(int* p, int v){
    asm volatile("st.release.cta.b32 [%0], %1;" :: "l"(p), "r"(v) : "memory");
}

// Emission slot for pair k (k = 0..127):
//   k <  64: slot = (k&1)*32 + (k>>1)            (role A: lane = k>>1)
//   k >= 64: slot = 64 + (k&1)*32 + ((k-64)>>1)  (role B)
// slot 128 = blank.

// ---------------------------------------------------------------------------
// K1: warp per (b,t) row: log2-softmax + gather of 129 tokens, staged through
// smem, written out as coalesced [b][g][slot][4] chunks (2 groups/block).
// Invalid-label rows (k >= tlen[b]) poisoned to NEGF -> K2 needs no masking.
// ---------------------------------------------------------------------------
__global__ void __launch_bounds__(256) k1_emit(const float* __restrict__ pred,
                                               const int* __restrict__ target,
                                               const int* __restrict__ tlen){
    __shared__ float sE[SLOTS_ * 12];          // [slot][tloc(8) pad->12]
    const int wid  = threadIdx.x >> 5;
    const int lane = threadIdx.x & 31;
    const int w    = blockIdx.x * 8 + wid;     // flat row = b*T + t
    const int b    = w >> 10;
    const int t    = w & (T_ - 1);
    const int tloc = t & 7;
    const int g0   = (t & ~7) >> 2;            // first of this block's 2 groups
    const float* p = pred + (size_t)w * V_;
    const int tl   = tlen[b];

    float4 v[8];
    float m = NEGF;
    #pragma unroll
    for (int k = 0; k < 8; k++){
        const int i4 = lane + 32 * k;
        if (i4 < 250){
            v[k] = reinterpret_cast<const float4*>(p)[i4];
            m = fmaxf(m, fmaxf(fmaxf(v[k].x, v[k].y), fmaxf(v[k].z, v[k].w)));
        } else {
            v[k] = make_float4(NEGF, NEGF, NEGF, NEGF);
        }
    }
    #pragma unroll
    for (int o = 16; o; o >>= 1) m = fmaxf(m, __shfl_xor_sync(~0u, m, o));

    float s = 0.f;
    #pragma unroll
    for (int k = 0; k < 8; k++){
        s += ex2f_((v[k].x - m) * L2E_) + ex2f_((v[k].y - m) * L2E_)
           + ex2f_((v[k].z - m) * L2E_) + ex2f_((v[k].w - m) * L2E_);
    }
    #pragma unroll
    for (int o = 16; o; o >>= 1) s += __shfl_xor_sync(~0u, s, o);
    const float lg2s = lg2f_(s);

    const int* tg = target + b * L_;
    #pragma unroll
    for (int r = lane; r < SLOTS_; r += 32){
        int slot; float val;
        if (r == 0){
            slot = 128;                                     // blank (token 0)
            val  = (p[0] - m) * L2E_ - lg2s;
        } else {
            const int k = r - 1;                            // pair index
            slot = (k < 64) ? (((k & 1) << 5) + (k >> 1))
                            : (64 + ((k & 1) << 5) + ((k - 64) >> 1));
            val  = (k < tl) ? ((p[tg[k]] - m) * L2E_ - lg2s) : NEGF;
        }
        sE[slot * 12 + tloc] = val;
    }
    __syncthreads();
    for (int k = threadIdx.x; k < 2 * SLOTS_; k += 256){
        const int gg = (k >= SLOTS_) ? 1 : 0;
        const int sl = k - gg * SLOTS_;
        const float4 o = *reinterpret_cast<const float4*>(&sE[sl * 12 + gg * 4]);
        reinterpret_cast<float4*>(g_E2)[((size_t)b * NG_ + g0 + gg) * SLOTS_ + sl] = o;
    }
}

// ---------------------------------------------------------------------------
// K2: W-CTC forward DP. 4 BATCHES PER BLOCK (8 warps, 256 threads) so each
// SMSP carries 2 warps -> latency of one warp hidden by the other.
// Per batch: 2 warps (role A: pairs 0-63, role B: 64-127), 2 pairs/lane,
// self-timed chunk handshake A->B via sBnd + release/acquire progress counter.
// Star state alpha[0] == 0 forever. Final blank bF (s=257, tl=128 only)
// reconstructed post-loop from sll + blank-emission prefix/suffix scans.
// End-star deferred to a final lse over per-step (alpha_t[ll], alpha_t[lb]).
// ---------------------------------------------------------------------------
__global__ void __launch_bounds__(256) k2_dp(const int* __restrict__ target,
                                             const int* __restrict__ tlen){
    extern __shared__ float dyn[];             // [3][4][1024] : sll, slb, sBnd
    __shared__ float red[4][2], sX[4][2];
    __shared__ int   sProg[4];
    const int tid  = threadIdx.x;
    const int warp = tid >> 5;
    const int lane = tid & 31;
    const int q    = warp >> 1;                // batch slot in block
    const int role = warp & 1;                 // 0 = A (pairs 0-63), 1 = B
    const int b    = blockIdx.x * 4 + q;
    float* sll  = dyn + q * T_;
    float* slb  = dyn + 4 * T_ + q * T_;
    float* sBnd = dyn + 8 * T_ + q * T_;
    const int tl   = tlen[b];                  // in [64,128]
    const int* tg  = target + b * L_;

    const int k0 = role * 64 + 2 * lane;       // my pair j=0
    const float sk0 = (k0 == 0 || tg[k0] != tg[k0 - 1]) ? 1.0f : 0.0f;
    const float sk1 = (tg[k0 + 1] != tg[k0]) ? 1.0f : 0.0f;

    const bool lbp  = (tl < 128);
    const bool wll0 = (k0 == tl - 1), wll1 = (k0 + 1 == tl - 1);
    const bool wlb0 = lbp && (k0 == tl), wlb1 = lbp && (k0 + 1 == tl);
    const bool bnd  = (role == 0 && lane == 31);   // pair-63 owner

    if (tid < 4) sProg[tid] = 0;
    __syncthreads();

    const float4* __restrict__ ch =
        reinterpret_cast<const float4*>(g_E2) + (size_t)b * NG_ * SLOTS_;
    const int sl0 = 64 * role + lane;
    const int sl1 = sl0 + 32;

    float bq0 = NEGF, lq0 = NEGF, bq1 = NEGF, lq1 = NEGF;
    float4 cb, c0, c1, pb, p0, p1;

    auto step = [&](float eb, float e0, float e1, float rb, int t){
        float sh = __shfl_up_sync(0xffffffffu, lq1, 1);
        const float lp0 = (lane == 0) ? ((role == 0) ? 0.0f : rb) : sh;
        const float lp1 = lq0;
        const float m0 = fmaxf(fmaxf(lq0, bq0), lp0);
        const float u0 = ex2f_(bq0 - m0), v0 = ex2f_(lp0 - m0), w0 = ex2f_(lq0 - m0);
        const float m1 = fmaxf(fmaxf(lq1, bq1), lp1);
        const float u1 = ex2f_(bq1 - m1), v1 = ex2f_(lp1 - m1), w1 = ex2f_(lq1 - m1);
        bq0 = eb + m0 + lg2f_(u0 + v0);
        lq0 = e0 + m0 + lg2f_(fmaf(v0, sk0, w0 + u0));
        bq1 = eb + m1 + lg2f_(u1 + v1);
        lq1 = e1 + m1 + lg2f_(fmaf(v1, sk1, w1 + u1));
        if (bnd) sBnd[t] = lq1;
        if (wll0 | wll1) sll[t] = wll1 ? lq1 : lq0;
        if (wlb0 | wlb1) slb[t] = wlb1 ? bq1 : bq0;
    };

    // ---- peeled group 0 ----
    if (role == 1 && lane == 0){               // chunk-0 wait
        while (ld_acq_(&sProg[q]) < 16) { __nanosleep(40); }
    }
    if (role == 1) __syncwarp();
    cb = ch[128]; c0 = ch[sl0]; c1 = ch[sl1];
    pb = ch[SLOTS_ + 128]; p0 = ch[SLOTS_ + sl0]; p1 = ch[SLOTS_ + sl1];
    if (role == 0 && lane == 0){ bq0 = cb.x; lq0 = c0.x; sll[0] = NEGF; slb[0] = NEGF; }
    if (bnd) sBnd[0] = lq1;                    // NEGF
    {
        float rb1 = 0.f, rb2 = 0.f, rb3 = 0.f;
        if (role == 1 && lane == 0){ rb1 = sBnd[0]; rb2 = sBnd[1]; rb3 = sBnd[2]; }
        step(cb.y, c0.y, c1.y, rb1, 1);
        step(cb.z, c0.z, c1.z, rb2, 2);
        step(cb.w, c0.w, c1.w, rb3, 3);
    }

    for (int g = 1; g < NG_; g++){
        if (role == 1 && (g & 3) == 0){        // chunk wait, once per 16 steps
            if (lane == 0){
                int need = 4 * (g + 4); if (need > T_) need = T_;
                while (ld_acq_(&sProg[q]) < need) { __nanosleep(40); }
            }
            __syncwarp();
        }
        cb = pb; c0 = p0; c1 = p1;
        if (g + 1 < NG_){
            const float4* cn = ch + (size_t)(g + 1) * SLOTS_;
            pb = cn[128]; p0 = cn[sl0]; p1 = cn[sl1];
        }
        float rb0 = 0.f, rb1 = 0.f, rb2 = 0.f, rb3 = 0.f;
        if (role == 1 && lane == 0){
            rb0 = sBnd[4 * g - 1]; rb1 = sBnd[4 * g];
            rb2 = sBnd[4 * g + 1]; rb3 = sBnd[4 * g + 2];
        }
        const int t0 = 4 * g;
        step(cb.x, c0.x, c1.x, rb0, t0);
        step(cb.y, c0.y, c1.y, rb1, t0 + 1);
        step(cb.z, c0.z, c1.z, rb2, t0 + 2);
        step(cb.w, c0.w, c1.w, rb3, t0 + 3);
        if (bnd && (g & 3) == 3) st_rel_(&sProg[q], 4 * (g + 1));
    }
    __syncthreads();

    // ---- tl==128: reconstruct slb (bF series) post-loop (barriers uniform) --
    const bool do128 = (tl == 128);
    const int  bt0   = (role * 32 + lane) * 16;
    float ebv[16], cbv[16], ps = 0.f, inc = 0.f;
    if (do128){
        #pragma unroll
        for (int i = 0; i < 16; i += 4){
            const float4 e4 = ch[(size_t)((bt0 + i) >> 2) * SLOTS_ + 128];
            ebv[i] = e4.x; ebv[i+1] = e4.y; ebv[i+2] = e4.z; ebv[i+3] = e4.w;
        }
        if (role == 0 && lane == 0) ebv[0] = 0.0f;   // eb_0 excluded
        #pragma unroll
        for (int i = 0; i < 16; i++) ps += ebv[i];
        inc = ps;                              // inclusive prefix across warp
        #pragma unroll
        for (int o = 1; o < 32; o <<= 1){
            const float v = __shfl_up_sync(~0u, inc, o);
            if (lane >= o) inc += v;
        }
        if (role == 0 && lane == 31) sX[q][0] = inc;
    }
    __syncthreads();
    float suf = NEGF;
    if (do128){
        float excl = inc - ps + ((role == 1) ? sX[q][0] : 0.f);
        float carry = excl, rmax = NEGF;
        #pragma unroll
        for (int i = 0; i < 16; i++){ carry += ebv[i]; cbv[i] = carry; rmax = fmaxf(rmax, carry); }
        float rsum = 0.f;
        #pragma unroll
        for (int i = 0; i < 16; i++) rsum += ex2f_(cbv[i] - rmax);
        suf = rmax + lg2f_(rsum);              // lse of CB over my 16 steps
        #pragma unroll
        for (int o = 1; o < 32; o <<= 1){
            const float v = __shfl_down_sync(~0u, suf, o);
            if (lane + o < 32) suf = lse2_(suf, v);
        }
        if (role == 1 && lane == 0) sX[q][1] = suf;
    }
    __syncthreads();
    if (do128){
        const float inclsuf = (role == 0) ? lse2_(suf, sX[q][1]) : suf;
        const float nx = __shfl_down_sync(~0u, inclsuf, 1);
        float c2 = (lane == 31) ? ((role == 0) ? sX[q][1] : NEGF) : nx;  // exclusive suffix
        #pragma unroll
        for (int i = 15; i >= 0; i--){
            const int t = bt0 + i;
            slb[t] = sll[t] - cbv[i] + c2;     // RB_t = c2 (lse of CB_u, u>t)
            c2 = lse2_(c2, cbv[i]);
        }
    }
    __syncthreads();

    // ---- final reduction: total = lse over 2048 stored values ----
    float m = NEGF;
    for (int t = role * 32 + lane; t < T_; t += 64) m = fmaxf(m, fmaxf(sll[t], slb[t]));
    #pragma unroll
    for (int o = 16; o; o >>= 1) m = fmaxf(m, __shfl_xor_sync(~0u, m, o));
    if (lane == 0) red[q][role] = m;
    __syncthreads();
    m = fmaxf(red[q][0], red[q][1]);
    float s = 0.f;
    for (int t = role * 32 + lane; t < T_; t += 64) s += ex2f_(sll[t] - m) + ex2f_(slb[t] - m);
    #pragma unroll
    for (int o = 16; o; o >>= 1) s += __shfl_xor_sync(~0u, s, o);
    __syncthreads();
    if (lane == 0) red[q][role] = s;
    __syncthreads();
    if (role == 0 && lane == 0){
        const float tot2 = m + lg2f_(red[q][0] + red[q][1]);
        g_partial[b] = (-tot2 * LN2_) / (float)tl;
    }
}

// ---------------------------------------------------------------------------
// K3: mean over batches -> scalar
// ---------------------------------------------------------------------------
__global__ void k3_final(float* __restrict__ out){
    float v = (threadIdx.x < B_) ? g_partial[threadIdx.x] : 0.f;
    #pragma unroll
    for (int o = 16; o; o >>= 1) v += __shfl_xor_sync(~0u, v, o);
    if (threadIdx.x == 0) out[0] = v / (float)B_;
}

extern "C" void kernel_launch(void* const* d_in, const int* in_sizes, int n_in,
                              void* d_out, int out_size) {
    const float* pred   = (const float*)d_in[0];   // (B,T,V) f32
    const int*   target = (const int*)d_in[1];     // (B,L) i32
    const int*   tlen   = (const int*)d_in[2];     // (B,) i32
    (void)in_sizes; (void)n_in; (void)out_size;

    const int k2smem = 12 * T_ * (int)sizeof(float);   // 48 KB
    cudaFuncSetAttribute(k2_dp, cudaFuncAttributeMaxDynamicSharedMemorySize, k2smem);

    k1_emit<<<B_ * T_ / 8, 256>>>(pred, target, tlen);
    k2_dp<<<B_ / 4, 256, k2smem>>>(target, tlen);
    k3_final<<<1, 32>>>((float*)d_out);
}

// round 9
// speedup vs baseline: 1.3771x; 1.3771x over previous
#include <cuda_runtime.h>
#include <cstdint>

#define B_ 32
#define T_ 1024
#define V_ 1000
#define L_ 128
#define NG_ 256           // time groups of 4 steps
#define SLOTS_ 129        // emission slots, 128 = blank
#define NEGF (-1e30f)
#define L2E_ 1.4426950408889634f
#define LN2_ 0.6931471805599453f

// scratch (allocation-free rule: __device__ globals)
// emissions, DP-native layout: [b][g][slot][4 timesteps], log2 domain
__device__ float g_E2[(size_t)B_ * NG_ * SLOTS_ * 4];
__device__ float g_partial[B_];

__device__ __forceinline__ float ex2f_(float x){ float y; asm("ex2.approx.f32 %0,%1;":"=f"(y):"f"(x)); return y; }
__device__ __forceinline__ float lg2f_(float x){ float y; asm("lg2.approx.f32 %0,%1;":"=f"(y):"f"(x)); return y; }
__device__ __forceinline__ float lse2_(float x, float y){
    float m = fmaxf(x, y);
    float d = fminf(x, y) - m;
    return m + lg2f_(1.0f + ex2f_(d));
}
__device__ __forceinline__ int ld_acq_(const int* p){
    int v; asm volatile("ld.acquire.cta.b32 %0, [%1];" : "=r"(v) : "l"(p) : "memory"); return v;
}
__device__ __forceinline__ void st_rel_(int* p, int v){
    asm volatile("st.release.cta.b32 [%0], %1;" :: "l"(p), "r"(v) : "memory");
}

// Emission slot for pair k (k = 0..127):
//   k <  64: slot = (k&1)*32 + (k>>1)            (role A: lane = k>>1)
//   k >= 64: slot = 64 + (k&1)*32 + ((k-64)>>1)  (role B)
// slot 128 = blank.

// ---------------------------------------------------------------------------
// K1: warp per (b,t) row: log2-softmax + gather of 129 tokens, staged through
// smem, written out as coalesced [b][g][slot][4] chunks (2 groups/block).
// Invalid-label rows (k >= tlen[b]) poisoned to NEGF -> K2 needs no masking.
// ---------------------------------------------------------------------------
__global__ void __launch_bounds__(256) k1_emit(const float* __restrict__ pred,
                                               const int* __restrict__ target,
                                               const int* __restrict__ tlen){
    __shared__ float sE[SLOTS_ * 12];          // [slot][tloc(8) pad->12]
    const int wid  = threadIdx.x >> 5;
    const int lane = threadIdx.x & 31;
    const int w    = blockIdx.x * 8 + wid;     // flat row = b*T + t
    const int b    = w >> 10;
    const int t    = w & (T_ - 1);
    const int tloc = t & 7;
    const int g0   = (t & ~7) >> 2;            // first of this block's 2 groups
    const float* p = pred + (size_t)w * V_;
    const int tl   = tlen[b];

    float4 v[8];
    float m = NEGF;
    #pragma unroll
    for (int k = 0; k < 8; k++){
        const int i4 = lane + 32 * k;
        if (i4 < 250){
            v[k] = reinterpret_cast<const float4*>(p)[i4];
            m = fmaxf(m, fmaxf(fmaxf(v[k].x, v[k].y), fmaxf(v[k].z, v[k].w)));
        } else {
            v[k] = make_float4(NEGF, NEGF, NEGF, NEGF);
        }
    }
    #pragma unroll
    for (int o = 16; o; o >>= 1) m = fmaxf(m, __shfl_xor_sync(~0u, m, o));

    float s = 0.f;
    #pragma unroll
    for (int k = 0; k < 8; k++){
        s += ex2f_((v[k].x - m) * L2E_) + ex2f_((v[k].y - m) * L2E_)
           + ex2f_((v[k].z - m) * L2E_) + ex2f_((v[k].w - m) * L2E_);
    }
    #pragma unroll
    for (int o = 16; o; o >>= 1) s += __shfl_xor_sync(~0u, s, o);
    const float lg2s = lg2f_(s);

    const int* tg = target + b * L_;
    #pragma unroll
    for (int r = lane; r < SLOTS_; r += 32){
        int slot; float val;
        if (r == 0){
            slot = 128;                                     // blank (token 0)
            val  = (p[0] - m) * L2E_ - lg2s;
        } else {
            const int k = r - 1;                            // pair index
            slot = (k < 64) ? (((k & 1) << 5) + (k >> 1))
                            : (64 + ((k & 1) << 5) + ((k - 64) >> 1));
            val  = (k < tl) ? ((p[tg[k]] - m) * L2E_ - lg2s) : NEGF;
        }
        sE[slot * 12 + tloc] = val;
    }
    __syncthreads();
    for (int k = threadIdx.x; k < 2 * SLOTS_; k += 256){
        const int gg = (k >= SLOTS_) ? 1 : 0;
        const int sl = k - gg * SLOTS_;
        const float4 o = *reinterpret_cast<const float4*>(&sE[sl * 12 + gg * 4]);
        reinterpret_cast<float4*>(g_E2)[((size_t)b * NG_ + g0 + gg) * SLOTS_ + sl] = o;
    }
}

// ---------------------------------------------------------------------------
// K2: W-CTC forward DP, 2 warps per batch, 2 pairs per lane, BRANCHLESS
// inner loop: all conditional stores replaced by mask-indexed unconditional
// STS (owner -> real array, everyone else -> shared dump word). No
// lane-divergent branch (=> no BSSY/BSYNC) inside the steady-state step.
// Warp A: pairs 0-63, warp B: pairs 64-127, B lagging A by one 16-step chunk
// (self-timed release/acquire handshake). Star state alpha[0] == 0 forever.
// Final blank bF (s=257, tl=128 only) reconstructed post-loop from sll +
// blank-emission prefix/suffix scans. End-star deferred to a final lse over
// per-step (alpha_t[ll], alpha_t[lb]).
// ---------------------------------------------------------------------------
__global__ void __launch_bounds__(64) k2_dp(const int* __restrict__ target,
                                            const int* __restrict__ tlen){
    __shared__ float sll[T_], slb[T_], sBnd[T_];
    __shared__ float dumpS;
    __shared__ float red[2], sX[2];
    __shared__ int   sProg;
    const int b    = blockIdx.x;
    const int tid  = threadIdx.x;
    const int wid  = tid >> 5;
    const int lane = tid & 31;
    const int tl   = tlen[b];                  // in [64,128]
    const int* tg  = target + b * L_;

    const int k0 = (wid == 0) ? 2 * lane : 64 + 2 * lane;   // my pair j=0
    const float sk0 = (k0 == 0 || tg[k0] != tg[k0 - 1]) ? 1.0f : 0.0f;
    const float sk1 = (tg[k0 + 1] != tg[k0]) ? 1.0f : 0.0f;

    const bool lbp  = (tl < 128);
    const bool wll0 = (k0 == tl - 1), wll1 = (k0 + 1 == tl - 1);
    const bool wlb0 = lbp && (k0 == tl), wlb1 = lbp && (k0 + 1 == tl);
    const bool bnd  = (wid == 0 && lane == 31);             // pair-63 owner

    // branchless store plumbing: ptr + index-mask per destination
    float* const pBnd = bnd ? sBnd : &dumpS;
    const int    mBnd = bnd ? ~0 : 0;
    float* const pll  = (wll0 | wll1) ? sll : &dumpS;
    const int    mll  = (wll0 | wll1) ? ~0 : 0;
    float* const plb  = (wlb0 | wlb1) ? slb : &dumpS;
    const int    mlb  = (wlb0 | wlb1) ? ~0 : 0;

    if (tid == 0) sProg = 0;
    __syncthreads();

    const float4* __restrict__ ch =
        reinterpret_cast<const float4*>(g_E2) + (size_t)b * NG_ * SLOTS_;
    const int sl0 = 64 * wid + lane;           // slot of pair j=0
    const int sl1 = sl0 + 32;                  // slot of pair j=1

    float bq0 = NEGF, lq0 = NEGF, bq1 = NEGF, lq1 = NEGF;
    float4 cb, c0, c1, pb, p0, p1;

    auto step = [&](float eb, float e0, float e1, float rb, int t){
        float sh = __shfl_up_sync(0xffffffffu, lq1, 1);
        const float lp0 = (lane == 0) ? ((wid == 0) ? 0.0f : rb) : sh;
        const float lp1 = lq0;
        const float m0 = fmaxf(fmaxf(lq0, bq0), lp0);
        const float u0 = ex2f_(bq0 - m0), v0 = ex2f_(lp0 - m0), w0 = ex2f_(lq0 - m0);
        const float m1 = fmaxf(fmaxf(lq1, bq1), lp1);
        const float u1 = ex2f_(bq1 - m1), v1 = ex2f_(lp1 - m1), w1 = ex2f_(lq1 - m1);
        bq0 = eb + m0 + lg2f_(u0 + v0);
        lq0 = e0 + m0 + lg2f_(fmaf(v0, sk0, w0 + u0));
        bq1 = eb + m1 + lg2f_(u1 + v1);
        lq1 = e1 + m1 + lg2f_(fmaf(v1, sk1, w1 + u1));
        pBnd[t & mBnd] = lq1;                  // unconditional, masked index
        pll [t & mll ] = wll1 ? lq1 : lq0;
        plb [t & mlb ] = wlb1 ? bq1 : bq0;
    };

    // ---- peeled group 0 ----
    if (wid == 1 && lane == 0){                // chunk-0 wait
        while (ld_acq_(&sProg) < 16) { __nanosleep(40); }
    }
    if (wid == 1) __syncwarp();
    cb = ch[128]; c0 = ch[sl0]; c1 = ch[sl1];
    pb = ch[SLOTS_ + 128]; p0 = ch[SLOTS_ + sl0]; p1 = ch[SLOTS_ + sl1];
    if (tid == 0){ bq0 = cb.x; lq0 = c0.x; sll[0] = NEGF; slb[0] = NEGF; }
    if (bnd) sBnd[0] = lq1;                    // NEGF
    {
        float rb1 = 0.f, rb2 = 0.f, rb3 = 0.f;
        if (wid == 1){ rb1 = sBnd[0]; rb2 = sBnd[1]; rb3 = sBnd[2]; }   // warp-uniform branch
        step(cb.y, c0.y, c1.y, rb1, 1);
        step(cb.z, c0.z, c1.z, rb2, 2);
        step(cb.w, c0.w, c1.w, rb3, 3);
    }

    for (int g = 1; g < NG_; g++){
        if (wid == 1 && (g & 3) == 0){         // chunk wait, once per 16 steps
            if (lane == 0){
                int need = 4 * (g + 4); if (need > T_) need = T_;
                while (ld_acq_(&sProg) < need) { __nanosleep(40); }
            }
            __syncwarp();
        }
        cb = pb; c0 = p0; c1 = p1;
        if (g + 1 < NG_){
            const float4* cn = ch + (size_t)(g + 1) * SLOTS_;
            pb = cn[128]; p0 = cn[sl0]; p1 = cn[sl1];
        }
        float rb0 = 0.f, rb1 = 0.f, rb2 = 0.f, rb3 = 0.f;
        if (wid == 1){                          // warp-uniform (broadcast LDS)
            rb0 = sBnd[4 * g - 1]; rb1 = sBnd[4 * g];
            rb2 = sBnd[4 * g + 1]; rb3 = sBnd[4 * g + 2];
        }
        const int t0 = 4 * g;
        step(cb.x, c0.x, c1.x, rb0, t0);
        step(cb.y, c0.y, c1.y, rb1, t0 + 1);
        step(cb.z, c0.z, c1.z, rb2, t0 + 2);
        step(cb.w, c0.w, c1.w, rb3, t0 + 3);
        if ((g & 3) == 3){ if (bnd) st_rel_(&sProg, 4 * (g + 1)); }
    }
    __syncthreads();

    // ---- tl==128: reconstruct slb (= bF series contribution) post-loop ----
    if (tl == 128){
        const int t0 = tid * 16;
        float ebv[16];
        #pragma unroll
        for (int i = 0; i < 16; i += 4){
            const float4 e4 = ch[(size_t)((t0 + i) >> 2) * SLOTS_ + 128];
            ebv[i] = e4.x; ebv[i+1] = e4.y; ebv[i+2] = e4.z; ebv[i+3] = e4.w;
        }
        if (tid == 0) ebv[0] = 0.0f;           // eb_0 excluded
        float ps = 0.f;
        #pragma unroll
        for (int i = 0; i < 16; i++) ps += ebv[i];
        float inc = ps;                        // inclusive prefix across tids
        #pragma unroll
        for (int o = 1; o < 32; o <<= 1){
            const float v = __shfl_up_sync(~0u, inc, o);
            if (lane >= o) inc += v;
        }
        if (wid == 0 && lane == 31) sX[0] = inc;
        __syncthreads();
        float excl = inc - ps + ((wid == 1) ? sX[0] : 0.f);
        float cbv[16];
        float carry = excl, rmax = NEGF;
        #pragma unroll
        for (int i = 0; i < 16; i++){ carry += ebv[i]; cbv[i] = carry; rmax = fmaxf(rmax, carry); }
        float rsum = 0.f;
        #pragma unroll
        for (int i = 0; i < 16; i++) rsum += ex2f_(cbv[i] - rmax);
        const float rtot = rmax + lg2f_(rsum); // lse of CB over my 16 steps
        float suf = rtot;                      // inclusive suffix lse across tids
        #pragma unroll
        for (int o = 1; o < 32; o <<= 1){
            const float v = __shfl_down_sync(~0u, suf, o);
            if (lane + o < 32) suf = lse2_(suf, v);
        }
        if (wid == 1 && lane == 0) sX[1] = suf;
        __syncthreads();
        const float inclsuf = (wid == 0) ? lse2_(suf, sX[1]) : suf;
        const float nx = __shfl_down_sync(~0u, inclsuf, 1);
        float c2 = (lane == 31) ? ((wid == 0) ? sX[1] : NEGF) : nx;  // exclusive suffix
        #pragma unroll
        for (int i = 15; i >= 0; i--){
            const int t = t0 + i;
            slb[t] = sll[t] - cbv[i] + c2;     // RB_t = c2 (lse of CB_u, u>t)
            c2 = lse2_(c2, cbv[i]);
        }
        __syncthreads();
    }

    // ---- final reduction: total = lse over 2048 stored values ----
    float m = NEGF;
    for (int t = tid; t < T_; t += 64) m = fmaxf(m, fmaxf(sll[t], slb[t]));
    #pragma unroll
    for (int o = 16; o; o >>= 1) m = fmaxf(m, __shfl_xor_sync(~0u, m, o));
    if (lane == 0) red[wid] = m;
    __syncthreads();
    m = fmaxf(red[0], red[1]);
    float s = 0.f;
    for (int t = tid; t < T_; t += 64) s += ex2f_(sll[t] - m) + ex2f_(slb[t] - m);
    #pragma unroll
    for (int o = 16; o; o >>= 1) s += __shfl_xor_sync(~0u, s, o);
    __syncthreads();
    if (lane == 0) red[wid] = s;
    __syncthreads();
    if (tid == 0){
        const float tot2 = m + lg2f_(red[0] + red[1]);
        g_partial[b] = (-tot2 * LN2_) / (float)tl;
    }
}

// ---------------------------------------------------------------------------
// K3: mean over batches -> scalar
// ---------------------------------------------------------------------------
__global__ void k3_final(float* __restrict__ out){
    float v = (threadIdx.x < B_) ? g_partial[threadIdx.x] : 0.f;
    #pragma unroll
    for (int o = 16; o; o >>= 1) v += __shfl_xor_sync(~0u, v, o);
    if (threadIdx.x == 0) out[0] = v / (float)B_;
}

extern "C" void kernel_launch(void* const* d_in, const int* in_sizes, int n_in,
                              void* d_out, int out_size) {
    const float* pred   = (const float*)d_in[0];   // (B,T,V) f32
    const int*   target = (const int*)d_in[1];     // (B,L) i32
    const int*   tlen   = (const int*)d_in[2];     // (B,) i32
    (void)in_sizes; (void)n_in; (void)out_size;

    k1_emit<<<B_ * T_ / 8, 256>>>(pred, target, tlen);
    k2_dp<<<B_, 64>>>(target, tlen);
    k3_final<<<1, 32>>>((float*)d_out);
}

// round 10
// speedup vs baseline: 1.4185x; 1.0301x over previous
#include <cuda_runtime.h>
#include <cstdint>

#define B_ 32
#define T_ 1024
#define V_ 1000
#define L_ 128
#define NG_ 256           // time groups of 4 steps
#define NI_ 288           // sheared slab count (max used: 255+31=286)
#define NEGF (-1e30f)
#define L2E_ 1.4426950408889634f
#define LN2_ 0.6931471805599453f

// scratch (allocation-free rule: __device__ globals)
// sheared emissions: slab i, row j (0..3), lane l holds pair 4l+j's 4 timesteps
// of group g = i - l  (log2 domain). Unwritten regions read as 0 (harmless).
__device__ float4 g_Esk[(size_t)B_ * NI_ * 4 * 32];
__device__ float  g_Blank[B_ * T_];       // blank log2-emission per (b,t)
__device__ float  g_partial[B_];

__device__ __forceinline__ float ex2f_(float x){ float y; asm("ex2.approx.f32 %0,%1;":"=f"(y):"f"(x)); return y; }
__device__ __forceinline__ float lg2f_(float x){ float y; asm("lg2.approx.f32 %0,%1;":"=f"(y):"f"(x)); return y; }
__device__ __forceinline__ float lse2_(float x, float y){
    float m = fmaxf(x, y);
    float d = fminf(x, y) - m;
    return m + lg2f_(1.0f + ex2f_(d));
}

// ---------------------------------------------------------------------------
// K1: warp per (b,t) row: log2-softmax + gather of 129 tokens. Blank goes
// straight to g_Blank; the 128 label values are staged in smem and written
// into the SHEARED slab layout g_Esk[b][g + (k>>2)][k&3][k>>2].
// Invalid-label rows (k >= tlen[b]) poisoned to NEGF -> K2 needs no masking.
// ---------------------------------------------------------------------------
__global__ void __launch_bounds__(256) k1_emit(const float* __restrict__ pred,
                                               const int* __restrict__ target,
                                               const int* __restrict__ tlen){
    __shared__ float sE[L_ * 12];              // [pair][tloc(8) pad->12]
    const int wid  = threadIdx.x >> 5;
    const int lane = threadIdx.x & 31;
    const int w    = blockIdx.x * 8 + wid;     // flat row = b*T + t
    const int b    = w >> 10;
    const int t    = w & (T_ - 1);
    const int tloc = t & 7;
    const int g0   = (t & ~7) >> 2;            // first of this block's 2 groups
    const float* p = pred + (size_t)w * V_;
    const int tl   = tlen[b];

    float4 v[8];
    float m = NEGF;
    #pragma unroll
    for (int k = 0; k < 8; k++){
        const int i4 = lane + 32 * k;
        if (i4 < 250){
            v[k] = reinterpret_cast<const float4*>(p)[i4];
            m = fmaxf(m, fmaxf(fmaxf(v[k].x, v[k].y), fmaxf(v[k].z, v[k].w)));
        } else {
            v[k] = make_float4(NEGF, NEGF, NEGF, NEGF);
        }
    }
    #pragma unroll
    for (int o = 16; o; o >>= 1) m = fmaxf(m, __shfl_xor_sync(~0u, m, o));

    float s = 0.f;
    #pragma unroll
    for (int k = 0; k < 8; k++){
        s += ex2f_((v[k].x - m) * L2E_) + ex2f_((v[k].y - m) * L2E_)
           + ex2f_((v[k].z - m) * L2E_) + ex2f_((v[k].w - m) * L2E_);
    }
    #pragma unroll
    for (int o = 16; o; o >>= 1) s += __shfl_xor_sync(~0u, s, o);
    const float lg2s = lg2f_(s);

    const int* tg = target + b * L_;
    #pragma unroll
    for (int r = lane; r < L_ + 1; r += 32){
        if (r == 0){
            g_Blank[w] = (p[0] - m) * L2E_ - lg2s;           // blank (token 0)
        } else {
            const int k = r - 1;                             // pair index
            const float val = (k < tl) ? ((p[tg[k]] - m) * L2E_ - lg2s) : NEGF;
            sE[k * 12 + tloc] = val;
        }
    }
    __syncthreads();
    // write 2 groups x 128 pairs into the sheared slab layout (one per thread)
    {
        const int x  = threadIdx.x;
        const int gg = x >> 7, k = x & 127;
        const float4 o = *reinterpret_cast<const float4*>(&sE[k * 12 + gg * 4]);
        const size_t i = (size_t)(g0 + gg + (k >> 2));
        g_Esk[(((size_t)b * NI_ + i) * 4 + (k & 3)) * 32 + (k >> 2)] = o;
    }
}

// ---------------------------------------------------------------------------
// K2: W-CTC forward DP, ONE warp per batch, IN-WARP TIME SKEW:
// lane l owns pairs 4l..4l+3 and processes time-group g = i - l at iteration
// i. The cross-lane boundary (lane l-1's pair-(4l-1) label at t-1) was
// produced one iteration earlier, so the iteration-top shfls read
// previous-iteration registers -> completely OFF the critical path. The hot
// loop has no sync, no divergent branch; masked stores route to per-lane
// dump slots. Star state alpha[0] == 0 forever; t=0 is a uniform step from
// an all-NEGF state. Final blank bF (s=257, tl=128 only) reconstructed
// post-loop from sll + blank-emission prefix/suffix scans. End-star deferred
// to a final lse over per-step (alpha_t[ll], alpha_t[lb]).
// ---------------------------------------------------------------------------
__global__ void __launch_bounds__(32) k2_dp(const int* __restrict__ target,
                                            const int* __restrict__ tlen){
    __shared__ float sll[T_], slb[T_];
    __shared__ float dump[32];
    const int b    = blockIdx.x;
    const int lane = threadIdx.x;
    const int tl   = tlen[b];                  // in [64,128]
    const int* tg  = target + b * L_;

    float sk[4];
    #pragma unroll
    for (int j = 0; j < 4; j++){
        const int k = 4 * lane + j;
        sk[j] = (k == 0 || tg[k] != tg[k - 1]) ? 1.0f : 0.0f;
    }

    const int  kll   = tl - 1,  jll = kll & 3;
    const bool ownll = ((kll >> 2) == lane);
    const bool lbp   = (tl < 128);
    const int  klb   = tl,      jlb = klb & 3;
    const bool ownlb = lbp && ((klb >> 2) == lane);
    const int  mll0  = ownll ? ~0 : 0;
    const int  mlb0  = ownlb ? ~0 : 0;

    const float4* __restrict__ E4 = g_Esk + (size_t)b * NI_ * 4 * 32;
    const float4* __restrict__ B4 = reinterpret_cast<const float4*>(g_Blank) + b * (T_ / 4);

    float bq0=NEGF,bq1=NEGF,bq2=NEGF,bq3=NEGF;
    float lq0=NEGF,lq1=NEGF,lq2=NEGF,lq3=NEGF;
    float h0=NEGF,h1=NEGF,h2=NEGF,h3=NEGF, carry=NEGF;

    float4 E0,E1,E2,E3,Eb, N0,N1,N2,N3,Nb;
    E0 = E4[lane]; E1 = E4[32+lane]; E2 = E4[64+lane]; E3 = E4[96+lane];
    Eb = B4[0];                                // g clamped to 0 for all lanes at i=0

    auto stepf = [&](float eb, float e0, float e1, float e2, float e3,
                     float lp0, int t, int mll, int mlb,
                     float* qll, float* qlb)->float{
        const float lp1 = lq0, lp2 = lq1, lp3 = lq2;
        float m, u, vv, w;
        m = fmaxf(fmaxf(lq0, bq0), lp0);
        u = ex2f_(bq0 - m); vv = ex2f_(lp0 - m); w = ex2f_(lq0 - m);
        bq0 = eb + m + lg2f_(u + vv);
        lq0 = e0 + m + lg2f_(fmaf(vv, sk[0], w + u));
        m = fmaxf(fmaxf(lq1, bq1), lp1);
        u = ex2f_(bq1 - m); vv = ex2f_(lp1 - m); w = ex2f_(lq1 - m);
        bq1 = eb + m + lg2f_(u + vv);
        lq1 = e1 + m + lg2f_(fmaf(vv, sk[1], w + u));
        m = fmaxf(fmaxf(lq2, bq2), lp2);
        u = ex2f_(bq2 - m); vv = ex2f_(lp2 - m); w = ex2f_(lq2 - m);
        bq2 = eb + m + lg2f_(u + vv);
        lq2 = e2 + m + lg2f_(fmaf(vv, sk[2], w + u));
        m = fmaxf(fmaxf(lq3, bq3), lp3);
        u = ex2f_(bq3 - m); vv = ex2f_(lp3 - m); w = ex2f_(lq3 - m);
        bq3 = eb + m + lg2f_(u + vv);
        lq3 = e3 + m + lg2f_(fmaf(vv, sk[3], w + u));
        const float vll = (jll & 2) ? ((jll & 1) ? lq3 : lq2) : ((jll & 1) ? lq1 : lq0);
        const float vlb = (jlb & 2) ? ((jlb & 1) ? bq3 : bq2) : ((jlb & 1) ? bq1 : bq0);
        qll[t & mll] = vll;
        qlb[t & mlb] = vlb;
        return lq3;
    };

    for (int i = 0; i < NG_ + 31; i++){
        if (i < NG_ + 30){                     // prefetch next slab + blank
            const float4* base = E4 + (size_t)(i + 1) * 128;
            N0 = base[lane]; N1 = base[32+lane]; N2 = base[64+lane]; N3 = base[96+lane];
            int gb = i + 1 - lane; gb = gb < 0 ? 0 : (gb > 255 ? 255 : gb);
            Nb = B4[gb];
        }
        // boundary: previous-iteration lq3 history of lane l-1 (off critical path)
        const float s0 = __shfl_up_sync(~0u, h0, 1);
        const float s1 = __shfl_up_sync(~0u, h1, 1);
        const float s2 = __shfl_up_sync(~0u, h2, 1);
        const float s3 = __shfl_up_sync(~0u, h3, 1);
        const bool  l0 = (lane == 0);
        const float bb0 = l0 ? 0.0f : carry;   // star boundary for lane 0
        const float bb1 = l0 ? 0.0f : s0;
        const float bb2 = l0 ? 0.0f : s1;
        const float bb3 = l0 ? 0.0f : s2;
        carry = l0 ? 0.0f : s3;

        const int g  = i - lane;
        const unsigned iw = ((unsigned)g < (unsigned)NG_) ? ~0u : 0u;
        const int mll = mll0 & (int)iw;
        const int mlb = mlb0 & (int)iw;
        float* qll = mll ? sll : &dump[lane];
        float* qlb = mlb ? slb : &dump[lane];
        const int t0 = 4 * g;

        h0 = stepf(Eb.x, E0.x, E1.x, E2.x, E3.x, bb0, t0,     mll, mlb, qll, qlb);
        h1 = stepf(Eb.y, E0.y, E1.y, E2.y, E3.y, bb1, t0 + 1, mll, mlb, qll, qlb);
        h2 = stepf(Eb.z, E0.z, E1.z, E2.z, E3.z, bb2, t0 + 2, mll, mlb, qll, qlb);
        h3 = stepf(Eb.w, E0.w, E1.w, E2.w, E3.w, bb3, t0 + 3, mll, mlb, qll, qlb);

        E0 = N0; E1 = N1; E2 = N2; E3 = N3; Eb = Nb;
    }
    __syncwarp();

    // ---- tl==128: reconstruct slb (= bF series contribution) post-loop ----
    if (tl == 128){
        const int t0 = lane * 32;
        float ebv[32];
        #pragma unroll
        for (int q = 0; q < 8; q++){
            const float4 e4 = B4[lane * 8 + q];
            ebv[4*q] = e4.x; ebv[4*q+1] = e4.y; ebv[4*q+2] = e4.z; ebv[4*q+3] = e4.w;
        }
        if (lane == 0) ebv[0] = 0.0f;          // eb_0 excluded
        float ps = 0.f;
        #pragma unroll
        for (int q = 0; q < 32; q++) ps += ebv[q];
        float inc = ps;                        // inclusive prefix across lanes
        #pragma unroll
        for (int o = 1; o < 32; o <<= 1){
            const float v = __shfl_up_sync(~0u, inc, o);
            if (lane >= o) inc += v;
        }
        const float excl = inc - ps;
        float cbv[32];
        float c = excl, rmax = NEGF;
        #pragma unroll
        for (int q = 0; q < 32; q++){ c += ebv[q]; cbv[q] = c; rmax = fmaxf(rmax, c); }
        float rsum = 0.f;
        #pragma unroll
        for (int q = 0; q < 32; q++) rsum += ex2f_(cbv[q] - rmax);
        float suf = rmax + lg2f_(rsum);        // lse of CB over my 32 steps
        #pragma unroll
        for (int o = 1; o < 32; o <<= 1){
            const float v = __shfl_down_sync(~0u, suf, o);
            if (lane + o < 32) suf = lse2_(suf, v);
        }
        const float nx = __shfl_down_sync(~0u, suf, 1);
        float c2 = (lane == 31) ? NEGF : nx;   // exclusive suffix lse
        #pragma unroll
        for (int q = 31; q >= 0; q--){
            const int t = t0 + q;
            slb[t] = sll[t] - cbv[q] + c2;     // RB_t = c2 (lse of CB_u, u>t)
            c2 = lse2_(c2, cbv[q]);
        }
    }
    __syncwarp();

    // ---- final reduction: total = lse over 2048 stored values ----
    float m = NEGF;
    for (int t = lane; t < T_; t += 32) m = fmaxf(m, fmaxf(sll[t], slb[t]));
    #pragma unroll
    for (int o = 16; o; o >>= 1) m = fmaxf(m, __shfl_xor_sync(~0u, m, o));
    float s = 0.f;
    for (int t = lane; t < T_; t += 32) s += ex2f_(sll[t] - m) + ex2f_(slb[t] - m);
    #pragma unroll
    for (int o = 16; o; o >>= 1) s += __shfl_xor_sync(~0u, s, o);
    if (lane == 0){
        const float tot2 = m + lg2f_(s);       // log2 likelihood
        g_partial[b] = (-tot2 * LN2_) / (float)tl;
    }
}

// ---------------------------------------------------------------------------
// K3: mean over batches -> scalar
// ---------------------------------------------------------------------------
__global__ void k3_final(float* __restrict__ out){
    float v = (threadIdx.x < B_) ? g_partial[threadIdx.x] : 0.f;
    #pragma unroll
    for (int o = 16; o; o >>= 1) v += __shfl_xor_sync(~0u, v, o);
    if (threadIdx.x == 0) out[0] = v / (float)B_;
}

// tiny no-op to shift ncu's capture alignment (diagnostic; ~1us)
__global__ void k_probe(){}

extern "C" void kernel_launch(void* const* d_in, const int* in_sizes, int n_in,
                              void* d_out, int out_size) {
    const float* pred   = (const float*)d_in[0];   // (B,T,V) f32
    const int*   target = (const int*)d_in[1];     // (B,L) i32
    const int*   tlen   = (const int*)d_in[2];     // (B,) i32
    (void)in_sizes; (void)n_in; (void)out_size;

    k1_emit<<<B_ * T_ / 8, 256>>>(pred, target, tlen);
    k2_dp<<<B_, 32>>>(target, tlen);
    k3_final<<<1, 32>>>((float*)d_out);
    k_probe<<<1, 1>>>();
}